// round 3
// baseline (speedup 1.0000x reference)
#include <cuda_runtime.h>
#include <math.h>

// Problem dims (fixed per reference)
#define BATCH 8
#define SEQ   2048
#define DIM   512
#define MSEQ  (BATCH * SEQ)        // 16384 rows for QKV projection

// GEMM tiling
#define BM 128
#define BN 128
#define BK 8
#define TM 8
#define TN 8
#define NTHREADS 256               // (BM/TM)*(BN/TN)

// Scratch (device globals; no runtime allocation allowed)
__device__ float g_Q[(size_t)MSEQ * DIM];                 // 32 MB
__device__ float g_K[(size_t)MSEQ * DIM];                 // 32 MB
__device__ float g_V[(size_t)MSEQ * DIM];                 // 32 MB
__device__ float g_S[(size_t)BATCH * SEQ * SEQ];          // 128 MB scores/attn

// ---------------------------------------------------------------------------
// NT GEMM: C[m,n] = sum_k A[m,k] * B[n,k] (+ bias[n])
// A: [M,K] row-major, B: [N,K] row-major, C: [M,N] row-major
// Batched via blockIdx.z with element strides sA/sB/sC.
// Requires M%BM==0, N%BN==0, K%BK==0 (true for all our shapes).
// ---------------------------------------------------------------------------
template <bool ADD_BIAS>
__global__ __launch_bounds__(NTHREADS)
void gemm_nt(const float* __restrict__ A, const float* __restrict__ B,
             const float* __restrict__ bias, float* __restrict__ C,
             int M, int N, int K,
             long long sA, long long sB, long long sC)
{
    __shared__ float As[BK][BM];
    __shared__ float Bs[BK][BN];

    const int tid = threadIdx.x;
    const int bm0 = blockIdx.y * BM;
    const int bn0 = blockIdx.x * BN;

    const float* Ab = A + (long long)blockIdx.z * sA;
    const float* Bb = B + (long long)blockIdx.z * sB;
    float*       Cb = C + (long long)blockIdx.z * sC;

    const int ty = tid >> 4;       // 0..15
    const int tx = tid & 15;       // 0..15

    // Loader mapping: 256 threads cover 128 rows x 8 k (two float4 per row)
    const int lrow = tid >> 1;          // 0..127
    const int lseg = (tid & 1) * 4;     // 0 or 4

    float acc[TM][TN];
#pragma unroll
    for (int i = 0; i < TM; ++i)
#pragma unroll
        for (int j = 0; j < TN; ++j) acc[i][j] = 0.0f;

    for (int k0 = 0; k0 < K; k0 += BK) {
        float4 av = *(const float4*)(Ab + (long long)(bm0 + lrow) * K + k0 + lseg);
        float4 bv = *(const float4*)(Bb + (long long)(bn0 + lrow) * K + k0 + lseg);

        __syncthreads();
        As[lseg + 0][lrow] = av.x;
        As[lseg + 1][lrow] = av.y;
        As[lseg + 2][lrow] = av.z;
        As[lseg + 3][lrow] = av.w;
        Bs[lseg + 0][lrow] = bv.x;
        Bs[lseg + 1][lrow] = bv.y;
        Bs[lseg + 2][lrow] = bv.z;
        Bs[lseg + 3][lrow] = bv.w;
        __syncthreads();

#pragma unroll
        for (int k = 0; k < BK; ++k) {
            float4 a0 = *(const float4*)&As[k][ty * TM];
            float4 a1 = *(const float4*)&As[k][ty * TM + 4];
            float4 b0 = *(const float4*)&Bs[k][tx * TN];
            float4 b1 = *(const float4*)&Bs[k][tx * TN + 4];
            float ra[TM] = {a0.x, a0.y, a0.z, a0.w, a1.x, a1.y, a1.z, a1.w};
            float rb[TN] = {b0.x, b0.y, b0.z, b0.w, b1.x, b1.y, b1.z, b1.w};
#pragma unroll
            for (int i = 0; i < TM; ++i)
#pragma unroll
                for (int j = 0; j < TN; ++j)
                    acc[i][j] = fmaf(ra[i], rb[j], acc[i][j]);
        }
    }

#pragma unroll
    for (int i = 0; i < TM; ++i) {
        const int m = bm0 + ty * TM + i;
        const int n0 = bn0 + tx * TN;
        float4 v0, v1;
        v0.x = acc[i][0]; v0.y = acc[i][1]; v0.z = acc[i][2]; v0.w = acc[i][3];
        v1.x = acc[i][4]; v1.y = acc[i][5]; v1.z = acc[i][6]; v1.w = acc[i][7];
        if (ADD_BIAS) {
            float4 c0 = *(const float4*)(bias + n0);
            float4 c1 = *(const float4*)(bias + n0 + 4);
            v0.x += c0.x; v0.y += c0.y; v0.z += c0.z; v0.w += c0.w;
            v1.x += c1.x; v1.y += c1.y; v1.z += c1.z; v1.w += c1.w;
        }
        *(float4*)(Cb + (long long)m * N + n0)     = v0;
        *(float4*)(Cb + (long long)m * N + n0 + 4) = v1;
    }
}

// ---------------------------------------------------------------------------
// NN GEMM: C[m,n] = sum_k A[m,k] * B[k,n]
// A: [M,K] row-major, B: [K,N] row-major, C: [M,N] row-major
// ---------------------------------------------------------------------------
__global__ __launch_bounds__(NTHREADS)
void gemm_nn(const float* __restrict__ A, const float* __restrict__ B,
             float* __restrict__ C,
             int M, int N, int K,
             long long sA, long long sB, long long sC)
{
    __shared__ float As[BK][BM];
    __shared__ float Bs[BK][BN];

    const int tid = threadIdx.x;
    const int bm0 = blockIdx.y * BM;
    const int bn0 = blockIdx.x * BN;

    const float* Ab = A + (long long)blockIdx.z * sA;
    const float* Bb = B + (long long)blockIdx.z * sB;
    float*       Cb = C + (long long)blockIdx.z * sC;

    const int ty = tid >> 4;
    const int tx = tid & 15;

    // A loader: 128 rows x 8 k
    const int larow = tid >> 1;
    const int laseg = (tid & 1) * 4;
    // B loader: 8 k-rows x 128 cols (float4 along n, fully coalesced)
    const int lbk   = tid >> 5;          // 0..7
    const int lbcol = (tid & 31) * 4;    // 0..124

    float acc[TM][TN];
#pragma unroll
    for (int i = 0; i < TM; ++i)
#pragma unroll
        for (int j = 0; j < TN; ++j) acc[i][j] = 0.0f;

    for (int k0 = 0; k0 < K; k0 += BK) {
        float4 av = *(const float4*)(Ab + (long long)(bm0 + larow) * K + k0 + laseg);
        float4 bv = *(const float4*)(Bb + (long long)(k0 + lbk) * N + bn0 + lbcol);

        __syncthreads();
        As[laseg + 0][larow] = av.x;
        As[laseg + 1][larow] = av.y;
        As[laseg + 2][larow] = av.z;
        As[laseg + 3][larow] = av.w;
        *(float4*)&Bs[lbk][lbcol] = bv;
        __syncthreads();

#pragma unroll
        for (int k = 0; k < BK; ++k) {
            float4 a0 = *(const float4*)&As[k][ty * TM];
            float4 a1 = *(const float4*)&As[k][ty * TM + 4];
            float4 b0 = *(const float4*)&Bs[k][tx * TN];
            float4 b1 = *(const float4*)&Bs[k][tx * TN + 4];
            float ra[TM] = {a0.x, a0.y, a0.z, a0.w, a1.x, a1.y, a1.z, a1.w};
            float rb[TN] = {b0.x, b0.y, b0.z, b0.w, b1.x, b1.y, b1.z, b1.w};
#pragma unroll
            for (int i = 0; i < TM; ++i)
#pragma unroll
                for (int j = 0; j < TN; ++j)
                    acc[i][j] = fmaf(ra[i], rb[j], acc[i][j]);
        }
    }

#pragma unroll
    for (int i = 0; i < TM; ++i) {
        const int m = bm0 + ty * TM + i;
        const int n0 = bn0 + tx * TN;
        float4 v0, v1;
        v0.x = acc[i][0]; v0.y = acc[i][1]; v0.z = acc[i][2]; v0.w = acc[i][3];
        v1.x = acc[i][4]; v1.y = acc[i][5]; v1.z = acc[i][6]; v1.w = acc[i][7];
        *(float4*)(Cb + (long long)m * N + n0)     = v0;
        *(float4*)(Cb + (long long)m * N + n0 + 4) = v1;
    }
}

// ---------------------------------------------------------------------------
// Masked softmax over rows of g_S (in place).
// Row = (b, q). scores -> mask[b,k]==0 ? -10000 : score*scale; softmax over k.
// One block per row; 256 threads hold 8 values each in registers.
// ---------------------------------------------------------------------------
__global__ __launch_bounds__(256)
void softmax_mask(float* __restrict__ S, const int* __restrict__ mask, float scale)
{
    const int row = blockIdx.x;          // 0 .. B*SEQ-1
    const int b   = row >> 11;           // row / SEQ
    float* srow = S + (size_t)row * SEQ;
    const int* mrow = mask + b * SEQ;
    const int tid = threadIdx.x;

    float v[8];
    float mx = -1e30f;
#pragma unroll
    for (int i = 0; i < 8; ++i) {
        const int k = tid + i * 256;
        const float s = (mrow[k] != 0) ? srow[k] * scale : -10000.0f;
        v[i] = s;
        mx = fmaxf(mx, s);
    }

    __shared__ float red[256];
    red[tid] = mx;
    __syncthreads();
#pragma unroll
    for (int s = 128; s > 0; s >>= 1) {
        if (tid < s) red[tid] = fmaxf(red[tid], red[tid + s]);
        __syncthreads();
    }
    mx = red[0];
    __syncthreads();

    float sum = 0.0f;
#pragma unroll
    for (int i = 0; i < 8; ++i) {
        v[i] = __expf(v[i] - mx);
        sum += v[i];
    }
    red[tid] = sum;
    __syncthreads();
#pragma unroll
    for (int s = 128; s > 0; s >>= 1) {
        if (tid < s) red[tid] += red[tid + s];
        __syncthreads();
    }
    const float inv = 1.0f / red[0];

#pragma unroll
    for (int i = 0; i < 8; ++i)
        srow[tid + i * 256] = v[i] * inv;
}

// ---------------------------------------------------------------------------
// Launch
// Inputs (metadata order): x, mask, Wq, bq, Wk, bk, Wv, bv
// ---------------------------------------------------------------------------
extern "C" void kernel_launch(void* const* d_in, const int* in_sizes, int n_in,
                              void* d_out, int out_size)
{
    (void)in_sizes; (void)n_in; (void)out_size;

    const float* x    = (const float*)d_in[0];
    const int*   mask = (const int*)  d_in[1];
    const float* Wq   = (const float*)d_in[2];
    const float* bq   = (const float*)d_in[3];
    const float* Wk   = (const float*)d_in[4];
    const float* bk   = (const float*)d_in[5];
    const float* Wv   = (const float*)d_in[6];
    const float* bv   = (const float*)d_in[7];
    float* out = (float*)d_out;

    float *pQ, *pK, *pV, *pS;
    cudaGetSymbolAddress((void**)&pQ, g_Q);
    cudaGetSymbolAddress((void**)&pK, g_K);
    cudaGetSymbolAddress((void**)&pV, g_V);
    cudaGetSymbolAddress((void**)&pS, g_S);

    const float scale = 1.0f / sqrtf((float)DIM);

    // 1) QKV projections: [16384,512] = x[16384,512] @ W^T + b   (NT)
    {
        dim3 grid(DIM / BN, MSEQ / BM, 1);
        gemm_nt<true><<<grid, NTHREADS>>>(x, Wq, bq, pQ, MSEQ, DIM, DIM, 0, 0, 0);
        gemm_nt<true><<<grid, NTHREADS>>>(x, Wk, bk, pK, MSEQ, DIM, DIM, 0, 0, 0);
        gemm_nt<true><<<grid, NTHREADS>>>(x, Wv, bv, pV, MSEQ, DIM, DIM, 0, 0, 0);
    }

    // 2) scores[b] = Q[b] @ K[b]^T   (NT, batched)
    {
        dim3 grid(SEQ / BN, SEQ / BM, BATCH);
        gemm_nt<false><<<grid, NTHREADS>>>(pQ, pK, nullptr, pS,
                                           SEQ, SEQ, DIM,
                                           (long long)SEQ * DIM,
                                           (long long)SEQ * DIM,
                                           (long long)SEQ * SEQ);
    }

    // 3) masked softmax (applies scale and -10000 mask), in place
    softmax_mask<<<BATCH * SEQ, 256>>>(pS, mask, scale);

    // 4) out[b] = attn[b] @ V[b]   (NN, batched)
    {
        dim3 grid(DIM / BN, SEQ / BM, BATCH);
        gemm_nn<<<grid, NTHREADS>>>(pS, pV, out,
                                    SEQ, DIM, SEQ,
                                    (long long)SEQ * SEQ,
                                    (long long)SEQ * DIM,
                                    (long long)SEQ * DIM);
    }
}

// round 5
// speedup vs baseline: 2.8867x; 2.8867x over previous
#include <cuda_runtime.h>
#include <math.h>
#include <stdint.h>

// Problem dims (fixed per reference)
#define BATCH 8
#define SEQ   2048
#define DIM   512
#define MSEQ  (BATCH * SEQ)

// GEMM tiling
#define BM 128
#define BN 128
#define BK 16
#define BKP 20     // BK + 4 pad  (row stride for m/n-major tiles; 20 -> conflict-free frag LDS)
#define BNP 136    // BN + 8 pad  (row stride for k-major B tile; 136 -> conflict-free frag LDS)
#define NTHREADS 256

// Scratch (device globals; no runtime allocation allowed)
__device__ float g_Q[(size_t)MSEQ * DIM];
__device__ float g_K[(size_t)MSEQ * DIM];
__device__ float g_V[(size_t)MSEQ * DIM];
__device__ float g_S[(size_t)BATCH * SEQ * SEQ];

// ---------------------------------------------------------------------------
// helpers
// ---------------------------------------------------------------------------
__device__ __forceinline__ uint32_t f2tf(float f) {
    uint32_t u;
    asm("cvt.rna.tf32.f32 %0, %1;" : "=r"(u) : "f"(f));
    return u;
}
__device__ __forceinline__ uint4 cvt4(float4 v) {
    uint4 u;
    u.x = f2tf(v.x); u.y = f2tf(v.y); u.z = f2tf(v.z); u.w = f2tf(v.w);
    return u;
}
__device__ __forceinline__ void mma_tf32(float c[4],
                                         uint32_t a0, uint32_t a1, uint32_t a2, uint32_t a3,
                                         uint32_t b0, uint32_t b1) {
    asm volatile(
        "mma.sync.aligned.m16n8k8.row.col.f32.tf32.tf32.f32 "
        "{%0,%1,%2,%3}, {%4,%5,%6,%7}, {%8,%9}, {%0,%1,%2,%3};\n"
        : "+f"(c[0]), "+f"(c[1]), "+f"(c[2]), "+f"(c[3])
        : "r"(a0), "r"(a1), "r"(a2), "r"(a3), "r"(b0), "r"(b1));
}

// ---------------------------------------------------------------------------
// TF32 tensor-core GEMM.
//   BT = true : C[m,n] = sum_k A[m,k] * B[n,k]   (NT; B row-major [N,K])
//   BT = false: C[m,n] = sum_k A[m,k] * B[k,n]   (NN; B row-major [K,N])
// Optional bias[n] added in epilogue. Batched via blockIdx.z strides.
// Requires M%128==0, N%128==0, K%16==0 (true for all shapes here).
//
// 256 threads = 8 warps as 2(m) x 4(n); warp tile 64x32; mma m16n8k8 tf32.
// Double-buffered shared tiles, register-staged global prefetch.
// ---------------------------------------------------------------------------
template <bool BT, bool ADD_BIAS>
__global__ __launch_bounds__(NTHREADS)
void gemm_tf32(const float* __restrict__ A, const float* __restrict__ B,
               const float* __restrict__ bias, float* __restrict__ C,
               int M, int N, int K,
               long long sA, long long sB, long long sC)
{
    constexpr int BSZ = BT ? (2 * BN * BKP) : (2 * BK * BNP);
    __shared__ uint32_t As[2][BM][BKP];   // m-major: As[buf][m][k]
    __shared__ uint32_t Bs[BSZ];          // BT: [buf][n][k] stride BKP ; NN: [buf][k][n] stride BNP

    const int tid  = threadIdx.x;
    const int lane = tid & 31;
    const int warp = tid >> 5;
    const int g    = lane >> 2;    // groupID 0..7
    const int tg   = lane & 3;     // thread-in-group 0..3
    const int wr   = warp >> 2;    // 0..1  (m)
    const int wc   = warp & 3;     // 0..3  (n)

    const int bm0 = blockIdx.y * BM;
    const int bn0 = blockIdx.x * BN;

    const float* Ab = A + (long long)blockIdx.z * sA;
    const float* Bb = B + (long long)blockIdx.z * sB;
    float*       Cb = C + (long long)blockIdx.z * sC;

    // A (and NT-B) loader: thread -> rows {ar, ar+64}, k-seg aseg (float4)
    const int ar   = tid >> 2;          // 0..63
    const int aseg = (tid & 3) * 4;     // 0,4,8,12
    // NN-B loader: 16 k-rows x 128 n
    const int bk_ = tid >> 4;           // 0..15
    const int bn_ = (tid & 15) * 4;     // 0..60 (and +64)

    float acc[4][4][4];
#pragma unroll
    for (int i = 0; i < 4; ++i)
#pragma unroll
        for (int j = 0; j < 4; ++j)
#pragma unroll
            for (int r = 0; r < 4; ++r) acc[i][j][r] = 0.0f;

    float4 pa0, pa1, pb0, pb1;

    auto loadG = [&](int k0) {
        pa0 = *(const float4*)(Ab + (long long)(bm0 + ar) * K + k0 + aseg);
        pa1 = *(const float4*)(Ab + (long long)(bm0 + ar + 64) * K + k0 + aseg);
        if (BT) {
            pb0 = *(const float4*)(Bb + (long long)(bn0 + ar) * K + k0 + aseg);
            pb1 = *(const float4*)(Bb + (long long)(bn0 + ar + 64) * K + k0 + aseg);
        } else {
            pb0 = *(const float4*)(Bb + (long long)(k0 + bk_) * N + bn0 + bn_);
            pb1 = *(const float4*)(Bb + (long long)(k0 + bk_) * N + bn0 + bn_ + 64);
        }
    };
    auto storeS = [&](int buf) {
        *(uint4*)&As[buf][ar][aseg]      = cvt4(pa0);
        *(uint4*)&As[buf][ar + 64][aseg] = cvt4(pa1);
        if (BT) {
            *(uint4*)&Bs[buf * BN * BKP + ar * BKP + aseg]        = cvt4(pb0);
            *(uint4*)&Bs[buf * BN * BKP + (ar + 64) * BKP + aseg] = cvt4(pb1);
        } else {
            *(uint4*)&Bs[buf * BK * BNP + bk_ * BNP + bn_]      = cvt4(pb0);
            *(uint4*)&Bs[buf * BK * BNP + bk_ * BNP + bn_ + 64] = cvt4(pb1);
        }
    };

    loadG(0);
    storeS(0);

    int buf = 0;
    for (int k0 = 0; k0 < K; k0 += BK) {
        __syncthreads();
        const bool more = (k0 + BK) < K;
        if (more) loadG(k0 + BK);

#pragma unroll
        for (int kk = 0; kk < BK; kk += 8) {
            uint32_t af[4][4];
            uint32_t bf[4][2];
#pragma unroll
            for (int fi = 0; fi < 4; ++fi) {
                const int m0 = wr * 64 + fi * 16;
                af[fi][0] = As[buf][m0 + g][kk + tg];
                af[fi][1] = As[buf][m0 + g + 8][kk + tg];
                af[fi][2] = As[buf][m0 + g][kk + tg + 4];
                af[fi][3] = As[buf][m0 + g + 8][kk + tg + 4];
            }
#pragma unroll
            for (int fj = 0; fj < 4; ++fj) {
                const int n0 = wc * 32 + fj * 8;
                if (BT) {
                    bf[fj][0] = Bs[buf * BN * BKP + (n0 + g) * BKP + kk + tg];
                    bf[fj][1] = Bs[buf * BN * BKP + (n0 + g) * BKP + kk + tg + 4];
                } else {
                    bf[fj][0] = Bs[buf * BK * BNP + (kk + tg) * BNP + n0 + g];
                    bf[fj][1] = Bs[buf * BK * BNP + (kk + tg + 4) * BNP + n0 + g];
                }
            }
#pragma unroll
            for (int fi = 0; fi < 4; ++fi)
#pragma unroll
                for (int fj = 0; fj < 4; ++fj)
                    mma_tf32(acc[fi][fj],
                             af[fi][0], af[fi][1], af[fi][2], af[fi][3],
                             bf[fj][0], bf[fj][1]);
        }

        if (more) storeS(buf ^ 1);
        buf ^= 1;
    }

    // Epilogue
#pragma unroll
    for (int fi = 0; fi < 4; ++fi) {
        const int mrow = bm0 + wr * 64 + fi * 16 + g;
#pragma unroll
        for (int fj = 0; fj < 4; ++fj) {
            const int n = bn0 + wc * 32 + fj * 8 + 2 * tg;
            float b0v = 0.0f, b1v = 0.0f;
            if (ADD_BIAS) { b0v = bias[n]; b1v = bias[n + 1]; }
            float2 v;
            v.x = acc[fi][fj][0] + b0v;
            v.y = acc[fi][fj][1] + b1v;
            *(float2*)(Cb + (long long)mrow * N + n) = v;
            v.x = acc[fi][fj][2] + b0v;
            v.y = acc[fi][fj][3] + b1v;
            *(float2*)(Cb + (long long)(mrow + 8) * N + n) = v;
        }
    }
}

// ---------------------------------------------------------------------------
// Masked softmax over rows of g_S (in place). Applies scale + mask like ref.
// ---------------------------------------------------------------------------
__global__ __launch_bounds__(256)
void softmax_mask(float* __restrict__ S, const int* __restrict__ mask, float scale)
{
    const int row = blockIdx.x;
    const int b   = row >> 11;
    float* srow = S + (size_t)row * SEQ;
    const int* mrow = mask + b * SEQ;
    const int tid = threadIdx.x;

    float v[8];
    float mx = -1e30f;
#pragma unroll
    for (int i = 0; i < 8; ++i) {
        const int k = tid + i * 256;
        const float s = (mrow[k] != 0) ? srow[k] * scale : -10000.0f;
        v[i] = s;
        mx = fmaxf(mx, s);
    }

    __shared__ float red[256];
    red[tid] = mx;
    __syncthreads();
#pragma unroll
    for (int s = 128; s > 0; s >>= 1) {
        if (tid < s) red[tid] = fmaxf(red[tid], red[tid + s]);
        __syncthreads();
    }
    mx = red[0];
    __syncthreads();

    float sum = 0.0f;
#pragma unroll
    for (int i = 0; i < 8; ++i) {
        v[i] = __expf(v[i] - mx);
        sum += v[i];
    }
    red[tid] = sum;
    __syncthreads();
#pragma unroll
    for (int s = 128; s > 0; s >>= 1) {
        if (tid < s) red[tid] += red[tid + s];
        __syncthreads();
    }
    const float inv = 1.0f / red[0];

#pragma unroll
    for (int i = 0; i < 8; ++i)
        srow[tid + i * 256] = v[i] * inv;
}

// ---------------------------------------------------------------------------
// Launch. Inputs (metadata order): x, mask, Wq, bq, Wk, bk, Wv, bv
// ---------------------------------------------------------------------------
extern "C" void kernel_launch(void* const* d_in, const int* in_sizes, int n_in,
                              void* d_out, int out_size)
{
    (void)in_sizes; (void)n_in; (void)out_size;

    const float* x    = (const float*)d_in[0];
    const int*   mask = (const int*)  d_in[1];
    const float* Wq   = (const float*)d_in[2];
    const float* bq   = (const float*)d_in[3];
    const float* Wk   = (const float*)d_in[4];
    const float* bk   = (const float*)d_in[5];
    const float* Wv   = (const float*)d_in[6];
    const float* bv   = (const float*)d_in[7];
    float* out = (float*)d_out;

    float *pQ, *pK, *pV, *pS;
    cudaGetSymbolAddress((void**)&pQ, g_Q);
    cudaGetSymbolAddress((void**)&pK, g_K);
    cudaGetSymbolAddress((void**)&pV, g_V);
    cudaGetSymbolAddress((void**)&pS, g_S);

    const float scale = 1.0f / sqrtf((float)DIM);

    // 1) QKV projections: [16384,512] = x @ W^T + b   (NT + bias)
    {
        dim3 grid(DIM / BN, MSEQ / BM, 1);
        gemm_tf32<true, true><<<grid, NTHREADS>>>(x, Wq, bq, pQ, MSEQ, DIM, DIM, 0, 0, 0);
        gemm_tf32<true, true><<<grid, NTHREADS>>>(x, Wk, bk, pK, MSEQ, DIM, DIM, 0, 0, 0);
        gemm_tf32<true, true><<<grid, NTHREADS>>>(x, Wv, bv, pV, MSEQ, DIM, DIM, 0, 0, 0);
    }

    // 2) scores[b] = Q[b] @ K[b]^T   (NT, batched)
    {
        dim3 grid(SEQ / BN, SEQ / BM, BATCH);
        gemm_tf32<true, false><<<grid, NTHREADS>>>(pQ, pK, nullptr, pS,
                                                   SEQ, SEQ, DIM,
                                                   (long long)SEQ * DIM,
                                                   (long long)SEQ * DIM,
                                                   (long long)SEQ * SEQ);
    }

    // 3) masked softmax (applies scale and -10000 mask), in place
    softmax_mask<<<BATCH * SEQ, 256>>>(pS, mask, scale);

    // 4) out[b] = attn[b] @ V[b]   (NN, batched)
    {
        dim3 grid(DIM / BN, SEQ / BM, BATCH);
        gemm_tf32<false, false><<<grid, NTHREADS>>>(pS, pV, nullptr, out,
                                                    SEQ, DIM, SEQ,
                                                    (long long)SEQ * SEQ,
                                                    (long long)SEQ * DIM,
                                                    (long long)SEQ * DIM);
    }
}

// round 7
// speedup vs baseline: 3.0723x; 1.0643x over previous
#include <cuda_runtime.h>
#include <cuda_fp16.h>
#include <math.h>
#include <stdint.h>

// Problem dims (fixed per reference)
#define BATCH 8
#define SEQ   2048
#define DIM   512
#define MSEQ  (BATCH * SEQ)

// Tiling: CTA 128x128, BK=32, 256 threads = 8 warps (2x4), warp tile 64x32
#define BM 128
#define BN 128
#define BK 32
#define NTHREADS 256
#define ROWB 80                       // padded row stride in bytes (32 fp16 = 64B data + 16B pad)
#define ATILE (128 * ROWB)            // 10240 B per buffer

// Scratch (device globals; no runtime allocation allowed)
__device__ __half g_Qh [(size_t)MSEQ * DIM];
__device__ __half g_Kh [(size_t)MSEQ * DIM];
__device__ __half g_VTh[(size_t)MSEQ * DIM];        // V transposed: [B][DIM][SEQ]
__device__ float  g_S  [(size_t)BATCH * SEQ * SEQ];

// ---------------------------------------------------------------------------
// asm helpers
// ---------------------------------------------------------------------------
__device__ __forceinline__ uint32_t smem_u32(const void* p) {
    uint32_t a;
    asm("{ .reg .u64 t; cvta.to.shared.u64 t, %1; cvt.u32.u64 %0, t; }" : "=r"(a) : "l"(p));
    return a;
}
#define LDSM4(r0, r1, r2, r3, addr) \
    asm volatile("ldmatrix.sync.aligned.m8n8.x4.shared.b16 {%0,%1,%2,%3}, [%4];" \
                 : "=r"(r0), "=r"(r1), "=r"(r2), "=r"(r3) : "r"(addr))
#define STS128(addr, u) \
    asm volatile("st.shared.v4.b32 [%0], {%1,%2,%3,%4};" \
                 :: "r"(addr), "r"((u).x), "r"((u).y), "r"((u).z), "r"((u).w))
#define MMA16816(c, a, b0v, b1v) \
    asm volatile("mma.sync.aligned.m16n8k16.row.col.f32.f16.f16.f32 " \
                 "{%0,%1,%2,%3}, {%4,%5,%6,%7}, {%8,%9}, {%0,%1,%2,%3};" \
                 : "+f"((c)[0]), "+f"((c)[1]), "+f"((c)[2]), "+f"((c)[3]) \
                 : "r"((a)[0]), "r"((a)[1]), "r"((a)[2]), "r"((a)[3]), \
                   "r"(b0v), "r"(b1v))

__device__ __forceinline__ uint32_t packh2(float a, float b) {
    __half2 h = __floats2half2_rn(a, b);
    return *(uint32_t*)&h;
}
__device__ __forceinline__ uint4 pack8(float4 a, float4 b) {
    uint4 u;
    u.x = packh2(a.x, a.y); u.y = packh2(a.z, a.w);
    u.z = packh2(b.x, b.y); u.w = packh2(b.z, b.w);
    return u;
}

// ---------------------------------------------------------------------------
// FP16 tensor-core NT GEMM: C[m,n] = (sum_k A[m,k]*B[n,k] + bias[n]) * scale
// A: [M,K] (lda), B: [N,K] (ldb), both K-major. Batched via blockIdx.z.
//   A_F32 / B_F32 : global operand dtype (f32 converted to fp16 at tile load)
//   OUT_MODE      : 0 = f32 row-major, 1 = fp16 row-major, 2 = fp16 transposed
//                   (mode 2: C is [B][DIM][SEQ], used for the V projection)
// ---------------------------------------------------------------------------
template <bool A_F32, bool B_F32, int OUT_MODE, bool ADD_BIAS>
__global__ __launch_bounds__(NTHREADS, 2)
void gemm_h(const void* __restrict__ A, const void* __restrict__ B,
            const float* __restrict__ bias, void* __restrict__ C,
            int lda, int ldb, int ldc, int Ksz, float scale,
            long long sA, long long sB, long long sC)
{
    __shared__ __align__(128) unsigned char smA[2 * ATILE];
    __shared__ __align__(128) unsigned char smB[2 * ATILE];
    const uint32_t aS = smem_u32(smA);
    const uint32_t bS = smem_u32(smB);

    const int tid  = threadIdx.x;
    const int lane = tid & 31;
    const int warp = tid >> 5;
    const int g    = lane >> 2;        // 0..7
    const int tg   = lane & 3;         // 0..3
    const int wr   = warp >> 2;        // 0..1 (m)
    const int wc   = warp & 3;         // 0..3 (n)
    const int lane_row = lane & 15;    // ldmatrix row within 16-row region
    const int lane_ck  = lane >> 4;    // ldmatrix 16B-chunk select (0/1)

    const int bm0 = blockIdx.y * BM;
    const int bn0 = blockIdx.x * BN;
    const long long z = blockIdx.z;

    const float*  Af = (const float*) A + z * sA;
    const __half* Ah = (const __half*)A + z * sA;
    const float*  Bf = (const float*) B + z * sB;
    const __half* Bh = (const __half*)B + z * sB;

    // Loader mapping: thread t -> row (t & 127), chunks ck0, ck0+1 (16 elems)
    const int lrow = tid & 127;
    const int lck0 = (tid >> 7) * 2;

    float4 agf[4]; uint4 agh[2];
    float4 bgf[4]; uint4 bgh[2];

    auto loadG = [&](int k0) {
        if (A_F32) {
            const float* p = Af + (long long)(bm0 + lrow) * lda + k0 + lck0 * 8;
            agf[0] = *(const float4*)(p);      agf[1] = *(const float4*)(p + 4);
            agf[2] = *(const float4*)(p + 8);  agf[3] = *(const float4*)(p + 12);
        } else {
            const uint4* p = (const uint4*)(Ah + (long long)(bm0 + lrow) * lda + k0 + lck0 * 8);
            agh[0] = p[0]; agh[1] = p[1];
        }
        if (B_F32) {
            const float* p = Bf + (long long)(bn0 + lrow) * ldb + k0 + lck0 * 8;
            bgf[0] = *(const float4*)(p);      bgf[1] = *(const float4*)(p + 4);
            bgf[2] = *(const float4*)(p + 8);  bgf[3] = *(const float4*)(p + 12);
        } else {
            const uint4* p = (const uint4*)(Bh + (long long)(bn0 + lrow) * ldb + k0 + lck0 * 8);
            bgh[0] = p[0]; bgh[1] = p[1];
        }
    };
    auto storeS = [&](int buf) {
        const uint32_t ab = aS + buf * ATILE + lrow * ROWB + lck0 * 16;
        const uint32_t bb = bS + buf * ATILE + lrow * ROWB + lck0 * 16;
        uint4 u0, u1, v0, v1;
        if (A_F32) { u0 = pack8(agf[0], agf[1]); u1 = pack8(agf[2], agf[3]); }
        else       { u0 = agh[0]; u1 = agh[1]; }
        if (B_F32) { v0 = pack8(bgf[0], bgf[1]); v1 = pack8(bgf[2], bgf[3]); }
        else       { v0 = bgh[0]; v1 = bgh[1]; }
        STS128(ab, u0); STS128(ab + 16, u1);
        STS128(bb, v0); STS128(bb + 16, v1);
    };

    float acc[4][4][4];
#pragma unroll
    for (int i = 0; i < 4; ++i)
#pragma unroll
        for (int j = 0; j < 4; ++j)
#pragma unroll
            for (int r = 0; r < 4; ++r) acc[i][j][r] = 0.0f;

    const int niter = Ksz / BK;

    loadG(0);
    storeS(0);

    for (int it = 0; it < niter; ++it) {
        const int buf = it & 1;
        __syncthreads();
        const bool more = (it + 1) < niter;
        if (more) loadG((it + 1) * BK);

        const uint32_t Ab32 = aS + buf * ATILE;
        const uint32_t Bb32 = bS + buf * ATILE;
#pragma unroll
        for (int kk = 0; kk < 2; ++kk) {           // two k16 steps per BK=32
            uint32_t af[4][4];
            uint32_t bf[4][2];
#pragma unroll
            for (int fi = 0; fi < 4; ++fi) {
                const uint32_t addr = Ab32
                    + (wr * 64 + fi * 16 + lane_row) * ROWB
                    + (kk * 2 + lane_ck) * 16;
                LDSM4(af[fi][0], af[fi][1], af[fi][2], af[fi][3], addr);
            }
#pragma unroll
            for (int fjp = 0; fjp < 2; ++fjp) {
                uint32_t t0, t1, t2, t3;
                const uint32_t addr = Bb32
                    + (wc * 32 + fjp * 16 + lane_row) * ROWB
                    + (kk * 2 + lane_ck) * 16;
                LDSM4(t0, t1, t2, t3, addr);
                bf[fjp * 2][0]     = t0;  bf[fjp * 2][1]     = t2;
                bf[fjp * 2 + 1][0] = t1;  bf[fjp * 2 + 1][1] = t3;
            }
#pragma unroll
            for (int fi = 0; fi < 4; ++fi)
#pragma unroll
                for (int fj = 0; fj < 4; ++fj)
                    MMA16816(acc[fi][fj], af[fi], bf[fj][0], bf[fj][1]);
        }
        if (more) storeS(buf ^ 1);
    }

    // ---------------- Epilogue ----------------
#pragma unroll
    for (int fi = 0; fi < 4; ++fi) {
        const int r0 = bm0 + wr * 64 + fi * 16 + g;
        const int r1 = r0 + 8;
#pragma unroll
        for (int fj = 0; fj < 4; ++fj) {
            const int n = bn0 + wc * 32 + fj * 8 + 2 * tg;
            float b0v = 0.0f, b1v = 0.0f;
            if (ADD_BIAS) { b0v = bias[n]; b1v = bias[n + 1]; }
            const float v00 = (acc[fi][fj][0] + b0v) * scale;
            const float v01 = (acc[fi][fj][1] + b1v) * scale;
            const float v10 = (acc[fi][fj][2] + b0v) * scale;
            const float v11 = (acc[fi][fj][3] + b1v) * scale;

            if (OUT_MODE == 0) {
                float* Cf = (float*)C + z * sC;
                *(float2*)(Cf + (long long)r0 * ldc + n) = make_float2(v00, v01);
                *(float2*)(Cf + (long long)r1 * ldc + n) = make_float2(v10, v11);
            } else if (OUT_MODE == 1) {
                __half* Ch = (__half*)C + z * sC;
                __half2 h0 = __floats2half2_rn(v00, v01);
                __half2 h1 = __floats2half2_rn(v10, v11);
                *(__half2*)(Ch + (long long)r0 * ldc + n) = h0;
                *(__half2*)(Ch + (long long)r1 * ldc + n) = h1;
            } else {
                // transposed: C[b][n][s], s = row % SEQ, b = row / SEQ
                __half* Ch = (__half*)C;
                const int b0i = r0 >> 11, s0 = r0 & (SEQ - 1);
                const int b1i = r1 >> 11, s1 = r1 & (SEQ - 1);
                __half* base0 = Ch + (long long)b0i * DIM * SEQ + s0;
                __half* base1 = Ch + (long long)b1i * DIM * SEQ + s1;
                base0[(long long)n * SEQ]       = __float2half_rn(v00);
                base0[(long long)(n + 1) * SEQ] = __float2half_rn(v01);
                base1[(long long)n * SEQ]       = __float2half_rn(v10);
                base1[(long long)(n + 1) * SEQ] = __float2half_rn(v11);
            }
        }
    }
}

// ---------------------------------------------------------------------------
// Masked softmax over rows of g_S (in place). Scale already folded into Q.
// ---------------------------------------------------------------------------
__global__ __launch_bounds__(256)
void softmax_mask(float* __restrict__ S, const int* __restrict__ mask)
{
    const int row = blockIdx.x;
    const int b   = row >> 11;
    float* srow = S + (size_t)row * SEQ;
    const int* mrow = mask + b * SEQ;
    const int tid = threadIdx.x;

    float v[8];
    float mx = -1e30f;
#pragma unroll
    for (int i = 0; i < 8; ++i) {
        const int k = tid + i * 256;
        const float s = (mrow[k] != 0) ? srow[k] : -10000.0f;
        v[i] = s;
        mx = fmaxf(mx, s);
    }

    __shared__ float red[256];
    red[tid] = mx;
    __syncthreads();
#pragma unroll
    for (int s = 128; s > 0; s >>= 1) {
        if (tid < s) red[tid] = fmaxf(red[tid], red[tid + s]);
        __syncthreads();
    }
    mx = red[0];
    __syncthreads();

    float sum = 0.0f;
#pragma unroll
    for (int i = 0; i < 8; ++i) {
        v[i] = __expf(v[i] - mx);
        sum += v[i];
    }
    red[tid] = sum;
    __syncthreads();
#pragma unroll
    for (int s = 128; s > 0; s >>= 1) {
        if (tid < s) red[tid] += red[tid + s];
        __syncthreads();
    }
    const float inv = 1.0f / red[0];

#pragma unroll
    for (int i = 0; i < 8; ++i)
        srow[tid + i * 256] = v[i] * inv;
}

// ---------------------------------------------------------------------------
// Launch. Inputs (metadata order): x, mask, Wq, bq, Wk, bk, Wv, bv
// ---------------------------------------------------------------------------
extern "C" void kernel_launch(void* const* d_in, const int* in_sizes, int n_in,
                              void* d_out, int out_size)
{
    (void)in_sizes; (void)n_in; (void)out_size;

    const float* x    = (const float*)d_in[0];
    const int*   mask = (const int*)  d_in[1];
    const float* Wq   = (const float*)d_in[2];
    const float* bq   = (const float*)d_in[3];
    const float* Wk   = (const float*)d_in[4];
    const float* bk   = (const float*)d_in[5];
    const float* Wv   = (const float*)d_in[6];
    const float* bv   = (const float*)d_in[7];
    float* out = (float*)d_out;

    __half *pQ, *pK, *pVT;
    float  *pS;
    cudaGetSymbolAddress((void**)&pQ,  g_Qh);
    cudaGetSymbolAddress((void**)&pK,  g_Kh);
    cudaGetSymbolAddress((void**)&pVT, g_VTh);
    cudaGetSymbolAddress((void**)&pS,  g_S);

    const float scale = 1.0f / sqrtf((float)DIM);

    // 1) QKV projections: fp16 outputs; scale folded into Q; V written transposed
    {
        dim3 g(DIM / BN, MSEQ / BM, 1);   // (4, 128, 1)
        gemm_h<true, true, 1, true><<<g, NTHREADS>>>(x, Wq, bq, pQ,  DIM, DIM, DIM, DIM, scale, 0, 0, 0);
        gemm_h<true, true, 1, true><<<g, NTHREADS>>>(x, Wk, bk, pK,  DIM, DIM, DIM, DIM, 1.0f,  0, 0, 0);
        gemm_h<true, true, 2, true><<<g, NTHREADS>>>(x, Wv, bv, pVT, DIM, DIM, 0,   DIM, 1.0f,  0, 0, 0);
    }

    // 2) scores[b] = Qs[b] @ K[b]^T  -> f32 S
    {
        dim3 g(SEQ / BN, SEQ / BM, BATCH);   // (16, 16, 8)
        gemm_h<false, false, 0, false><<<g, NTHREADS>>>(pQ, pK, nullptr, pS,
                                                        DIM, DIM, SEQ, DIM, 1.0f,
                                                        (long long)SEQ * DIM,
                                                        (long long)SEQ * DIM,
                                                        (long long)SEQ * SEQ);
    }

    // 3) masked softmax (mask -> -10000), in place, f32
    softmax_mask<<<BATCH * SEQ, 256>>>(pS, mask);

    // 4) out[b] = attn[b] @ VT[b]^T  (NT: VT is [DIM][SEQ] K-major), f32 out
    {
        dim3 g(DIM / BN, SEQ / BM, BATCH);   // (4, 16, 8)
        gemm_h<true, false, 0, false><<<g, NTHREADS>>>(pS, pVT, nullptr, out,
                                                       SEQ, SEQ, DIM, SEQ, 1.0f,
                                                       (long long)SEQ * SEQ,
                                                       (long long)DIM * SEQ,
                                                       (long long)SEQ * DIM);
    }
}

// round 9
// speedup vs baseline: 3.4410x; 1.1200x over previous
#include <cuda_runtime.h>
#include <cuda_fp16.h>
#include <math.h>
#include <stdint.h>

// Problem dims (fixed per reference)
#define BATCH 8
#define SEQ   2048
#define DIM   512
#define MSEQ  (BATCH * SEQ)

#define BM 128
#define BN 128
#define NTHREADS 256

// Scratch (device globals; no runtime allocation allowed)
__device__ __half g_Qh [(size_t)MSEQ * DIM];
__device__ __half g_Kh [(size_t)MSEQ * DIM];
__device__ __half g_VTh[(size_t)MSEQ * DIM];        // V transposed: [B][DIM][SEQ]
__device__ __half g_Ph [(size_t)BATCH * SEQ * SEQ]; // softmax probs fp16
__device__ float  g_S  [(size_t)BATCH * SEQ * SEQ]; // raw scores f32

// ---------------------------------------------------------------------------
// asm helpers
// ---------------------------------------------------------------------------
__device__ __forceinline__ uint32_t smem_u32(const void* p) {
    uint32_t a;
    asm("{ .reg .u64 t; cvta.to.shared.u64 t, %1; cvt.u32.u64 %0, t; }" : "=r"(a) : "l"(p));
    return a;
}
#define LDSM4(r0, r1, r2, r3, addr) \
    asm volatile("ldmatrix.sync.aligned.m8n8.x4.shared.b16 {%0,%1,%2,%3}, [%4];" \
                 : "=r"(r0), "=r"(r1), "=r"(r2), "=r"(r3) : "r"(addr))
#define STS128(addr, u) \
    asm volatile("st.shared.v4.b32 [%0], {%1,%2,%3,%4};" \
                 :: "r"(addr), "r"((u).x), "r"((u).y), "r"((u).z), "r"((u).w))
#define MMA16816(c, a, b0v, b1v) \
    asm volatile("mma.sync.aligned.m16n8k16.row.col.f32.f16.f16.f32 " \
                 "{%0,%1,%2,%3}, {%4,%5,%6,%7}, {%8,%9}, {%0,%1,%2,%3};" \
                 : "+f"((c)[0]), "+f"((c)[1]), "+f"((c)[2]), "+f"((c)[3]) \
                 : "r"((a)[0]), "r"((a)[1]), "r"((a)[2]), "r"((a)[3]), \
                   "r"(b0v), "r"(b1v))
#define CPASYNC16(dst, src) \
    asm volatile("cp.async.cg.shared.global [%0], [%1], 16;" :: "r"(dst), "l"(src))
#define CPCOMMIT() asm volatile("cp.async.commit_group;" ::: "memory")
#define CPWAIT0()  asm volatile("cp.async.wait_group 0;"  ::: "memory")

__device__ __forceinline__ uint32_t packh2(float a, float b) {
    __half2 h = __floats2half2_rn(a, b);
    return *(uint32_t*)&h;
}
__device__ __forceinline__ uint4 pack8(float4 a, float4 b) {
    uint4 u;
    u.x = packh2(a.x, a.y); u.y = packh2(a.z, a.w);
    u.z = packh2(b.x, b.y); u.w = packh2(b.z, b.w);
    return u;
}

// ===========================================================================
// Kernel 1: fp16-in GEMM with cp.async + SW128 swizzle. NT, C = f32.
//   C[m,n] = sum_k A[m,k]*B[n,k].  BK=64, double-buffered, 2 CTAs/SM.
//   smem: [A0 | A1 | B0 | B1], each 128 rows x 128B, swizzled.
// ===========================================================================
#define HTILE 16384
#define HSMEM (4 * HTILE)

__global__ __launch_bounds__(NTHREADS, 2)
void gemm_h16(const __half* __restrict__ A, const __half* __restrict__ B,
              float* __restrict__ C,
              int lda, int ldb, int ldc, int Ksz,
              long long sA, long long sB, long long sC)
{
    extern __shared__ unsigned char hsm[];
    const uint32_t aS = smem_u32(hsm);
    const uint32_t bS = aS + 2 * HTILE;

    const int tid  = threadIdx.x;
    const int lane = tid & 31;
    const int warp = tid >> 5;
    const int g    = lane >> 2;
    const int tg   = lane & 3;
    const int wr   = warp >> 2;
    const int wc   = warp & 3;
    const int lane_row = lane & 15;
    const int lane_ck  = lane >> 4;

    const int bm0 = blockIdx.y * BM;
    const int bn0 = blockIdx.x * BN;
    const long long z = blockIdx.z;

    // loader: thread -> row (tid&127), 4 chunks of 16B at c = (tid>>7)*4 + j
    const int lrow = tid & 127;
    const int lc0  = (tid >> 7) * 4;
    const __half* Arow = A + z * sA + (long long)(bm0 + lrow) * lda;
    const __half* Brow = B + z * sB + (long long)(bn0 + lrow) * ldb;
    const int rx = lrow & 7;                         // swizzle row bits

    auto issue = [&](int k0, int buf) {
        const uint32_t ab = aS + buf * HTILE + lrow * 128;
        const uint32_t bb = bS + buf * HTILE + lrow * 128;
#pragma unroll
        for (int j = 0; j < 4; ++j) {
            const int c = lc0 + j;
            const uint32_t so = (uint32_t)((c ^ rx) << 4);
            CPASYNC16(ab + so, Arow + k0 + c * 8);
            CPASYNC16(bb + so, Brow + k0 + c * 8);
        }
        CPCOMMIT();
    };

    float acc[4][4][4];
#pragma unroll
    for (int i = 0; i < 4; ++i)
#pragma unroll
        for (int j = 0; j < 4; ++j)
#pragma unroll
            for (int r = 0; r < 4; ++r) acc[i][j][r] = 0.0f;

    const int niter = Ksz / 64;
    issue(0, 0);

    for (int it = 0; it < niter; ++it) {
        const int buf = it & 1;
        CPWAIT0();
        __syncthreads();
        if (it + 1 < niter) issue((it + 1) * 64, buf ^ 1);

        const uint32_t Ab32 = aS + buf * HTILE;
        const uint32_t Bb32 = bS + buf * HTILE;
        const int arx = lane_row & 7;
#pragma unroll
        for (int kk = 0; kk < 4; ++kk) {            // four k16 steps per BK=64
            const int ck = kk * 2 + lane_ck;
            uint32_t af[4][4];
            uint32_t bf[4][2];
#pragma unroll
            for (int fi = 0; fi < 4; ++fi) {
                const uint32_t addr = Ab32
                    + (wr * 64 + fi * 16 + lane_row) * 128
                    + ((ck ^ arx) << 4);
                LDSM4(af[fi][0], af[fi][1], af[fi][2], af[fi][3], addr);
            }
#pragma unroll
            for (int fjp = 0; fjp < 2; ++fjp) {
                uint32_t t0, t1, t2, t3;
                const uint32_t addr = Bb32
                    + (wc * 32 + fjp * 16 + lane_row) * 128
                    + ((ck ^ arx) << 4);
                LDSM4(t0, t1, t2, t3, addr);
                bf[fjp * 2][0]     = t0;  bf[fjp * 2][1]     = t2;
                bf[fjp * 2 + 1][0] = t1;  bf[fjp * 2 + 1][1] = t3;
            }
#pragma unroll
            for (int fi = 0; fi < 4; ++fi)
#pragma unroll
                for (int fj = 0; fj < 4; ++fj)
                    MMA16816(acc[fi][fj], af[fi], bf[fj][0], bf[fj][1]);
        }
    }

    // Epilogue: f32 row-major
    float* Cf = C + z * sC;
#pragma unroll
    for (int fi = 0; fi < 4; ++fi) {
        const int r0 = bm0 + wr * 64 + fi * 16 + g;
        const int r1 = r0 + 8;
#pragma unroll
        for (int fj = 0; fj < 4; ++fj) {
            const int n = bn0 + wc * 32 + fj * 8 + 2 * tg;
            *(float2*)(Cf + (long long)r0 * ldc + n) = make_float2(acc[fi][fj][0], acc[fi][fj][1]);
            *(float2*)(Cf + (long long)r1 * ldc + n) = make_float2(acc[fi][fj][2], acc[fi][fj][3]);
        }
    }
}

// ===========================================================================
// Kernel 2: f32-in projection GEMM (R7 design, proven): NT, fp16 out.
//   OUT_MODE 1 = fp16 row-major; 2 = fp16 transposed [B][DIM][SEQ].
// ===========================================================================
#define ROWB 80
#define ATILE (128 * ROWB)

template <int OUT_MODE>
__global__ __launch_bounds__(NTHREADS, 2)
void gemm_proj(const float* __restrict__ A, const float* __restrict__ B,
               const float* __restrict__ bias, __half* __restrict__ C,
               int lda, int ldb, int ldc, int Ksz, float scale)
{
    __shared__ __align__(128) unsigned char smA[2 * ATILE];
    __shared__ __align__(128) unsigned char smB[2 * ATILE];
    const uint32_t aS = smem_u32(smA);
    const uint32_t bS = smem_u32(smB);

    const int tid  = threadIdx.x;
    const int lane = tid & 31;
    const int warp = tid >> 5;
    const int g    = lane >> 2;
    const int tg   = lane & 3;
    const int wr   = warp >> 2;
    const int wc   = warp & 3;
    const int lane_row = lane & 15;
    const int lane_ck  = lane >> 4;

    const int bm0 = blockIdx.y * BM;
    const int bn0 = blockIdx.x * BN;

    const int lrow = tid & 127;
    const int lck0 = (tid >> 7) * 2;

    float4 agf[4], bgf[4];

    auto loadG = [&](int k0) {
        const float* p = A + (long long)(bm0 + lrow) * lda + k0 + lck0 * 8;
        agf[0] = *(const float4*)(p);      agf[1] = *(const float4*)(p + 4);
        agf[2] = *(const float4*)(p + 8);  agf[3] = *(const float4*)(p + 12);
        const float* q = B + (long long)(bn0 + lrow) * ldb + k0 + lck0 * 8;
        bgf[0] = *(const float4*)(q);      bgf[1] = *(const float4*)(q + 4);
        bgf[2] = *(const float4*)(q + 8);  bgf[3] = *(const float4*)(q + 12);
    };
    auto storeS = [&](int buf) {
        const uint32_t ab = aS + buf * ATILE + lrow * ROWB + lck0 * 16;
        const uint32_t bb = bS + buf * ATILE + lrow * ROWB + lck0 * 16;
        uint4 u0 = pack8(agf[0], agf[1]), u1 = pack8(agf[2], agf[3]);
        uint4 v0 = pack8(bgf[0], bgf[1]), v1 = pack8(bgf[2], bgf[3]);
        STS128(ab, u0); STS128(ab + 16, u1);
        STS128(bb, v0); STS128(bb + 16, v1);
    };

    float acc[4][4][4];
#pragma unroll
    for (int i = 0; i < 4; ++i)
#pragma unroll
        for (int j = 0; j < 4; ++j)
#pragma unroll
            for (int r = 0; r < 4; ++r) acc[i][j][r] = 0.0f;

    const int niter = Ksz / 32;
    loadG(0);
    storeS(0);

    for (int it = 0; it < niter; ++it) {
        const int buf = it & 1;
        __syncthreads();
        const bool more = (it + 1) < niter;
        if (more) loadG((it + 1) * 32);

        const uint32_t Ab32 = aS + buf * ATILE;
        const uint32_t Bb32 = bS + buf * ATILE;
#pragma unroll
        for (int kk = 0; kk < 2; ++kk) {
            uint32_t af[4][4];
            uint32_t bf[4][2];
#pragma unroll
            for (int fi = 0; fi < 4; ++fi) {
                const uint32_t addr = Ab32
                    + (wr * 64 + fi * 16 + lane_row) * ROWB
                    + (kk * 2 + lane_ck) * 16;
                LDSM4(af[fi][0], af[fi][1], af[fi][2], af[fi][3], addr);
            }
#pragma unroll
            for (int fjp = 0; fjp < 2; ++fjp) {
                uint32_t t0, t1, t2, t3;
                const uint32_t addr = Bb32
                    + (wc * 32 + fjp * 16 + lane_row) * ROWB
                    + (kk * 2 + lane_ck) * 16;
                LDSM4(t0, t1, t2, t3, addr);
                bf[fjp * 2][0]     = t0;  bf[fjp * 2][1]     = t2;
                bf[fjp * 2 + 1][0] = t1;  bf[fjp * 2 + 1][1] = t3;
            }
#pragma unroll
            for (int fi = 0; fi < 4; ++fi)
#pragma unroll
                for (int fj = 0; fj < 4; ++fj)
                    MMA16816(acc[fi][fj], af[fi], bf[fj][0], bf[fj][1]);
        }
        if (more) storeS(buf ^ 1);
    }

#pragma unroll
    for (int fi = 0; fi < 4; ++fi) {
        const int r0 = bm0 + wr * 64 + fi * 16 + g;
        const int r1 = r0 + 8;
#pragma unroll
        for (int fj = 0; fj < 4; ++fj) {
            const int n = bn0 + wc * 32 + fj * 8 + 2 * tg;
            const float b0v = bias[n], b1v = bias[n + 1];
            const float v00 = (acc[fi][fj][0] + b0v) * scale;
            const float v01 = (acc[fi][fj][1] + b1v) * scale;
            const float v10 = (acc[fi][fj][2] + b0v) * scale;
            const float v11 = (acc[fi][fj][3] + b1v) * scale;
            if (OUT_MODE == 1) {
                *(__half2*)(C + (long long)r0 * ldc + n) = __floats2half2_rn(v00, v01);
                *(__half2*)(C + (long long)r1 * ldc + n) = __floats2half2_rn(v10, v11);
            } else {
                const int b0i = r0 >> 11, s0 = r0 & (SEQ - 1);
                const int b1i = r1 >> 11, s1 = r1 & (SEQ - 1);
                __half* base0 = C + (long long)b0i * DIM * SEQ + s0;
                __half* base1 = C + (long long)b1i * DIM * SEQ + s1;
                base0[(long long)n * SEQ]       = __float2half_rn(v00);
                base0[(long long)(n + 1) * SEQ] = __float2half_rn(v01);
                base1[(long long)n * SEQ]       = __float2half_rn(v10);
                base1[(long long)(n + 1) * SEQ] = __float2half_rn(v11);
            }
        }
    }
}

// ===========================================================================
// Masked softmax: S f32 in -> P fp16 out. Scale folded into Q upstream.
// Thread t handles 8 consecutive elems (vectorized ld/st).
// ===========================================================================
__global__ __launch_bounds__(256)
void softmax_h(const float* __restrict__ S, __half* __restrict__ P,
               const int* __restrict__ mask)
{
    const int row = blockIdx.x;
    const int b   = row >> 11;
    const float* srow = S + (size_t)row * SEQ;
    __half*      prow = P + (size_t)row * SEQ;
    const int*   mrow = mask + b * SEQ;
    const int tid = threadIdx.x;
    const int base = tid * 8;

    float4 s0 = *(const float4*)(srow + base);
    float4 s1 = *(const float4*)(srow + base + 4);
    int4   m0 = *(const int4*)(mrow + base);
    int4   m1 = *(const int4*)(mrow + base + 4);

    float v[8];
    v[0] = m0.x ? s0.x : -10000.0f;
    v[1] = m0.y ? s0.y : -10000.0f;
    v[2] = m0.z ? s0.z : -10000.0f;
    v[3] = m0.w ? s0.w : -10000.0f;
    v[4] = m1.x ? s1.x : -10000.0f;
    v[5] = m1.y ? s1.y : -10000.0f;
    v[6] = m1.z ? s1.z : -10000.0f;
    v[7] = m1.w ? s1.w : -10000.0f;

    float mx = v[0];
#pragma unroll
    for (int i = 1; i < 8; ++i) mx = fmaxf(mx, v[i]);

    __shared__ float red[256];
    red[tid] = mx;
    __syncthreads();
#pragma unroll
    for (int s = 128; s > 0; s >>= 1) {
        if (tid < s) red[tid] = fmaxf(red[tid], red[tid + s]);
        __syncthreads();
    }
    mx = red[0];
    __syncthreads();

    float sum = 0.0f;
#pragma unroll
    for (int i = 0; i < 8; ++i) {
        v[i] = __expf(v[i] - mx);
        sum += v[i];
    }
    red[tid] = sum;
    __syncthreads();
#pragma unroll
    for (int s = 128; s > 0; s >>= 1) {
        if (tid < s) red[tid] += red[tid + s];
        __syncthreads();
    }
    const float inv = 1.0f / red[0];

    uint4 o;
    o.x = packh2(v[0] * inv, v[1] * inv);
    o.y = packh2(v[2] * inv, v[3] * inv);
    o.z = packh2(v[4] * inv, v[5] * inv);
    o.w = packh2(v[6] * inv, v[7] * inv);
    *(uint4*)(prow + base) = o;
}

// ---------------------------------------------------------------------------
// Launch. Inputs (metadata order): x, mask, Wq, bq, Wk, bk, Wv, bv
// ---------------------------------------------------------------------------
extern "C" void kernel_launch(void* const* d_in, const int* in_sizes, int n_in,
                              void* d_out, int out_size)
{
    (void)in_sizes; (void)n_in; (void)out_size;

    const float* x    = (const float*)d_in[0];
    const int*   mask = (const int*)  d_in[1];
    const float* Wq   = (const float*)d_in[2];
    const float* bq   = (const float*)d_in[3];
    const float* Wk   = (const float*)d_in[4];
    const float* bk   = (const float*)d_in[5];
    const float* Wv   = (const float*)d_in[6];
    const float* bv   = (const float*)d_in[7];
    float* out = (float*)d_out;

    __half *pQ, *pK, *pVT, *pP;
    float  *pS;
    cudaGetSymbolAddress((void**)&pQ,  g_Qh);
    cudaGetSymbolAddress((void**)&pK,  g_Kh);
    cudaGetSymbolAddress((void**)&pVT, g_VTh);
    cudaGetSymbolAddress((void**)&pP,  g_Ph);
    cudaGetSymbolAddress((void**)&pS,  g_S);

    cudaFuncSetAttribute(gemm_h16, cudaFuncAttributeMaxDynamicSharedMemorySize, HSMEM);

    const float scale = 1.0f / sqrtf((float)DIM);

    // 1) QKV projections: fp16 outputs; scale folded into Q; V written transposed
    {
        dim3 g(DIM / BN, MSEQ / BM, 1);   // (4, 128, 1)
        gemm_proj<1><<<g, NTHREADS>>>(x, Wq, bq, pQ,  DIM, DIM, DIM, DIM, scale);
        gemm_proj<1><<<g, NTHREADS>>>(x, Wk, bk, pK,  DIM, DIM, DIM, DIM, 1.0f);
        gemm_proj<2><<<g, NTHREADS>>>(x, Wv, bv, pVT, DIM, DIM, 0,   DIM, 1.0f);
    }

    // 2) scores[b] = Qs[b] @ K[b]^T  -> f32 S
    {
        dim3 g(SEQ / BN, SEQ / BM, BATCH);   // (16, 16, 8)
        gemm_h16<<<g, NTHREADS, HSMEM>>>(pQ, pK, pS,
                                         DIM, DIM, SEQ, DIM,
                                         (long long)SEQ * DIM,
                                         (long long)SEQ * DIM,
                                         (long long)SEQ * SEQ);
    }

    // 3) masked softmax: S f32 -> P fp16
    softmax_h<<<BATCH * SEQ, 256>>>(pS, pP, mask);

    // 4) out[b] = P[b] @ VT[b]^T  (NT: VT is [DIM][SEQ] K-major), f32 out
    {
        dim3 g(DIM / BN, SEQ / BM, BATCH);   // (4, 16, 8)
        gemm_h16<<<g, NTHREADS, HSMEM>>>(pP, pVT, out,
                                         SEQ, SEQ, DIM, SEQ,
                                         (long long)SEQ * SEQ,
                                         (long long)DIM * SEQ,
                                         (long long)SEQ * DIM);
    }
}

// round 11
// speedup vs baseline: 3.9036x; 1.1344x over previous
#include <cuda_runtime.h>
#include <cuda_fp16.h>
#include <math.h>
#include <stdint.h>

// Problem dims (fixed per reference)
#define BATCH 8
#define SEQ   2048
#define DIM   512
#define MSEQ  (BATCH * SEQ)

#define BM 128
#define BN 128
#define NTHREADS 256

// 3-stage pipeline smem
#define HTILE 16384                   // one operand tile: 128 rows x 128B
#define STAGE_BYTES (2 * HTILE)
#define STAGES 3
#define HSMEM (STAGES * STAGE_BYTES)  // 96 KB

// Scratch (device globals; no runtime allocation allowed)
__device__ __half g_xh [(size_t)MSEQ * DIM];        // x in fp16
__device__ __half g_Wqh[(size_t)DIM * DIM];
__device__ __half g_Wkh[(size_t)DIM * DIM];
__device__ __half g_Wvh[(size_t)DIM * DIM];
__device__ __half g_Qh [(size_t)MSEQ * DIM];
__device__ __half g_Kh [(size_t)MSEQ * DIM];
__device__ __half g_VTh[(size_t)MSEQ * DIM];        // V transposed: [B][DIM][SEQ]
__device__ __half g_Ph [(size_t)BATCH * SEQ * SEQ]; // softmax probs fp16
__device__ float  g_S  [(size_t)BATCH * SEQ * SEQ]; // raw scores f32

// ---------------------------------------------------------------------------
// asm helpers
// ---------------------------------------------------------------------------
__device__ __forceinline__ uint32_t smem_u32(const void* p) {
    uint32_t a;
    asm("{ .reg .u64 t; cvta.to.shared.u64 t, %1; cvt.u32.u64 %0, t; }" : "=r"(a) : "l"(p));
    return a;
}
#define LDSM4(r0, r1, r2, r3, addr) \
    asm volatile("ldmatrix.sync.aligned.m8n8.x4.shared.b16 {%0,%1,%2,%3}, [%4];" \
                 : "=r"(r0), "=r"(r1), "=r"(r2), "=r"(r3) : "r"(addr))
#define MMA16816(c, a, b0v, b1v) \
    asm volatile("mma.sync.aligned.m16n8k16.row.col.f32.f16.f16.f32 " \
                 "{%0,%1,%2,%3}, {%4,%5,%6,%7}, {%8,%9}, {%0,%1,%2,%3};" \
                 : "+f"((c)[0]), "+f"((c)[1]), "+f"((c)[2]), "+f"((c)[3]) \
                 : "r"((a)[0]), "r"((a)[1]), "r"((a)[2]), "r"((a)[3]), \
                   "r"(b0v), "r"(b1v))
#define CPASYNC16(dst, src) \
    asm volatile("cp.async.cg.shared.global [%0], [%1], 16;" :: "r"(dst), "l"(src))
#define CPCOMMIT() asm volatile("cp.async.commit_group;" ::: "memory")
#define CPWAIT1()  asm volatile("cp.async.wait_group 1;"  ::: "memory")

__device__ __forceinline__ uint32_t packh2(float a, float b) {
    __half2 h = __floats2half2_rn(a, b);
    return *(uint32_t*)&h;
}
__device__ __forceinline__ uint4 pack8(float4 a, float4 b) {
    uint4 u;
    u.x = packh2(a.x, a.y); u.y = packh2(a.z, a.w);
    u.z = packh2(b.x, b.y); u.w = packh2(b.z, b.w);
    return u;
}

// ===========================================================================
// f32 -> fp16 conversion (8 elems/thread, fully coalesced)
// ===========================================================================
__global__ __launch_bounds__(256)
void cvt_f2h(const float* __restrict__ in, __half* __restrict__ out, int n)
{
    const int i = (blockIdx.x * 256 + threadIdx.x) * 8;
    if (i < n) {
        float4 a = *(const float4*)(in + i);
        float4 b = *(const float4*)(in + i + 4);
        *(uint4*)(out + i) = pack8(a, b);
    }
}

// ===========================================================================
// Unified fp16 tensor-core NT GEMM, cp.async 3-stage, SW128 swizzle.
//   C[m,n] = (sum_k A[m,k]*B[n,k] + bias[n]) * scale
//   OUT_MODE: 0 = f32 row-major, 1 = fp16 row-major, 2 = fp16 transposed
//             (mode 2: C is [B][DIM][SEQ]; used for the V projection)
//   BK = 64, 256 threads = 8 warps (2m x 4n), warp tile 64x32, 2 CTAs/SM.
// ===========================================================================
template <int OUT_MODE, bool ADD_BIAS>
__global__ __launch_bounds__(NTHREADS, 2)
void gemm_h16(const __half* __restrict__ A, const __half* __restrict__ B,
              const float* __restrict__ bias, void* __restrict__ C,
              int lda, int ldb, int ldc, int Ksz, float scale,
              long long sA, long long sB, long long sC)
{
    extern __shared__ unsigned char hsm[];
    const uint32_t sb0 = smem_u32(hsm);

    const int tid  = threadIdx.x;
    const int lane = tid & 31;
    const int warp = tid >> 5;
    const int g    = lane >> 2;
    const int tg   = lane & 3;
    const int wr   = warp >> 2;
    const int wc   = warp & 3;
    const int lane_row = lane & 15;
    const int lane_ck  = lane >> 4;

    const int bm0 = blockIdx.y * BM;
    const int bn0 = blockIdx.x * BN;
    const long long z = blockIdx.z;

    // loader: thread -> row (tid&127), 4 chunks of 16B at c = (tid>>7)*4 + j
    const int lrow = tid & 127;
    const int lc0  = (tid >> 7) * 4;
    const __half* Arow = A + z * sA + (long long)(bm0 + lrow) * lda;
    const __half* Brow = B + z * sB + (long long)(bn0 + lrow) * ldb;
    const int rx = lrow & 7;                         // swizzle row bits

    auto issue = [&](int k0, int s) {
        const uint32_t ab = sb0 + s * STAGE_BYTES + lrow * 128;
        const uint32_t bb = ab + HTILE;
#pragma unroll
        for (int j = 0; j < 4; ++j) {
            const int c = lc0 + j;
            const uint32_t so = (uint32_t)((c ^ rx) << 4);
            CPASYNC16(ab + so, Arow + k0 + c * 8);
            CPASYNC16(bb + so, Brow + k0 + c * 8);
        }
        CPCOMMIT();
    };

    float acc[4][4][4];
#pragma unroll
    for (int i = 0; i < 4; ++i)
#pragma unroll
        for (int j = 0; j < 4; ++j)
#pragma unroll
            for (int r = 0; r < 4; ++r) acc[i][j][r] = 0.0f;

    const int niter = Ksz / 64;                      // >= 8 for all shapes here
    issue(0, 0);
    issue(64, 1);

    const int arx = lane_row & 7;

    for (int it = 0; it < niter; ++it) {
        const int s = it % STAGES;
        CPWAIT1();                                   // stage `it` complete
        __syncthreads();
        if (it + 2 < niter) issue((it + 2) * 64, (it + 2) % STAGES);
        else                CPCOMMIT();              // keep group count uniform

        const uint32_t Ab32 = sb0 + s * STAGE_BYTES;
        const uint32_t Bb32 = Ab32 + HTILE;
#pragma unroll
        for (int kk = 0; kk < 4; ++kk) {             // four k16 steps per BK=64
            const int ck = kk * 2 + lane_ck;
            uint32_t af[4][4];
            uint32_t bf[4][2];
#pragma unroll
            for (int fi = 0; fi < 4; ++fi) {
                const uint32_t addr = Ab32
                    + (wr * 64 + fi * 16 + lane_row) * 128
                    + ((ck ^ arx) << 4);
                LDSM4(af[fi][0], af[fi][1], af[fi][2], af[fi][3], addr);
            }
#pragma unroll
            for (int fjp = 0; fjp < 2; ++fjp) {
                uint32_t t0, t1, t2, t3;
                const uint32_t addr = Bb32
                    + (wc * 32 + fjp * 16 + lane_row) * 128
                    + ((ck ^ arx) << 4);
                LDSM4(t0, t1, t2, t3, addr);
                bf[fjp * 2][0]     = t0;  bf[fjp * 2][1]     = t2;
                bf[fjp * 2 + 1][0] = t1;  bf[fjp * 2 + 1][1] = t3;
            }
#pragma unroll
            for (int fi = 0; fi < 4; ++fi)
#pragma unroll
                for (int fj = 0; fj < 4; ++fj)
                    MMA16816(acc[fi][fj], af[fi], bf[fj][0], bf[fj][1]);
        }
    }

    // ---------------- Epilogue ----------------
#pragma unroll
    for (int fi = 0; fi < 4; ++fi) {
        const int r0 = bm0 + wr * 64 + fi * 16 + g;
        const int r1 = r0 + 8;
#pragma unroll
        for (int fj = 0; fj < 4; ++fj) {
            const int n = bn0 + wc * 32 + fj * 8 + 2 * tg;
            float b0v = 0.0f, b1v = 0.0f;
            if (ADD_BIAS) { b0v = bias[n]; b1v = bias[n + 1]; }
            const float v00 = (acc[fi][fj][0] + b0v) * scale;
            const float v01 = (acc[fi][fj][1] + b1v) * scale;
            const float v10 = (acc[fi][fj][2] + b0v) * scale;
            const float v11 = (acc[fi][fj][3] + b1v) * scale;

            if (OUT_MODE == 0) {
                float* Cf = (float*)C + z * sC;
                *(float2*)(Cf + (long long)r0 * ldc + n) = make_float2(v00, v01);
                *(float2*)(Cf + (long long)r1 * ldc + n) = make_float2(v10, v11);
            } else if (OUT_MODE == 1) {
                __half* Ch = (__half*)C + z * sC;
                *(__half2*)(Ch + (long long)r0 * ldc + n) = __floats2half2_rn(v00, v01);
                *(__half2*)(Ch + (long long)r1 * ldc + n) = __floats2half2_rn(v10, v11);
            } else {
                __half* Ch = (__half*)C;
                const int b0i = r0 >> 11, s0 = r0 & (SEQ - 1);
                const int b1i = r1 >> 11, s1 = r1 & (SEQ - 1);
                __half* base0 = Ch + (long long)b0i * DIM * SEQ + s0;
                __half* base1 = Ch + (long long)b1i * DIM * SEQ + s1;
                base0[(long long)n * SEQ]       = __float2half_rn(v00);
                base0[(long long)(n + 1) * SEQ] = __float2half_rn(v01);
                base1[(long long)n * SEQ]       = __float2half_rn(v10);
                base1[(long long)(n + 1) * SEQ] = __float2half_rn(v11);
            }
        }
    }
}

// ===========================================================================
// Masked softmax: S f32 in -> P fp16 out. Scale folded into Q upstream.
// ===========================================================================
__global__ __launch_bounds__(256)
void softmax_h(const float* __restrict__ S, __half* __restrict__ P,
               const int* __restrict__ mask)
{
    const int row = blockIdx.x;
    const int b   = row >> 11;
    const float* srow = S + (size_t)row * SEQ;
    __half*      prow = P + (size_t)row * SEQ;
    const int*   mrow = mask + b * SEQ;
    const int tid = threadIdx.x;
    const int base = tid * 8;

    float4 s0 = *(const float4*)(srow + base);
    float4 s1 = *(const float4*)(srow + base + 4);
    int4   m0 = *(const int4*)(mrow + base);
    int4   m1 = *(const int4*)(mrow + base + 4);

    float v[8];
    v[0] = m0.x ? s0.x : -10000.0f;
    v[1] = m0.y ? s0.y : -10000.0f;
    v[2] = m0.z ? s0.z : -10000.0f;
    v[3] = m0.w ? s0.w : -10000.0f;
    v[4] = m1.x ? s1.x : -10000.0f;
    v[5] = m1.y ? s1.y : -10000.0f;
    v[6] = m1.z ? s1.z : -10000.0f;
    v[7] = m1.w ? s1.w : -10000.0f;

    float mx = v[0];
#pragma unroll
    for (int i = 1; i < 8; ++i) mx = fmaxf(mx, v[i]);

    __shared__ float red[256];
    red[tid] = mx;
    __syncthreads();
#pragma unroll
    for (int s = 128; s > 0; s >>= 1) {
        if (tid < s) red[tid] = fmaxf(red[tid], red[tid + s]);
        __syncthreads();
    }
    mx = red[0];
    __syncthreads();

    float sum = 0.0f;
#pragma unroll
    for (int i = 0; i < 8; ++i) {
        v[i] = __expf(v[i] - mx);
        sum += v[i];
    }
    red[tid] = sum;
    __syncthreads();
#pragma unroll
    for (int s = 128; s > 0; s >>= 1) {
        if (tid < s) red[tid] += red[tid + s];
        __syncthreads();
    }
    const float inv = 1.0f / red[0];

    uint4 o;
    o.x = packh2(v[0] * inv, v[1] * inv);
    o.y = packh2(v[2] * inv, v[3] * inv);
    o.z = packh2(v[4] * inv, v[5] * inv);
    o.w = packh2(v[6] * inv, v[7] * inv);
    *(uint4*)(prow + base) = o;
}

// ---------------------------------------------------------------------------
// Launch. Inputs (metadata order): x, mask, Wq, bq, Wk, bk, Wv, bv
// ---------------------------------------------------------------------------
extern "C" void kernel_launch(void* const* d_in, const int* in_sizes, int n_in,
                              void* d_out, int out_size)
{
    (void)in_sizes; (void)n_in; (void)out_size;

    const float* x    = (const float*)d_in[0];
    const int*   mask = (const int*)  d_in[1];
    const float* Wq   = (const float*)d_in[2];
    const float* bq   = (const float*)d_in[3];
    const float* Wk   = (const float*)d_in[4];
    const float* bk   = (const float*)d_in[5];
    const float* Wv   = (const float*)d_in[6];
    const float* bv   = (const float*)d_in[7];
    float* out = (float*)d_out;

    __half *pxh, *pWq, *pWk, *pWv, *pQ, *pK, *pVT, *pP;
    float  *pS;
    cudaGetSymbolAddress((void**)&pxh, g_xh);
    cudaGetSymbolAddress((void**)&pWq, g_Wqh);
    cudaGetSymbolAddress((void**)&pWk, g_Wkh);
    cudaGetSymbolAddress((void**)&pWv, g_Wvh);
    cudaGetSymbolAddress((void**)&pQ,  g_Qh);
    cudaGetSymbolAddress((void**)&pK,  g_Kh);
    cudaGetSymbolAddress((void**)&pVT, g_VTh);
    cudaGetSymbolAddress((void**)&pP,  g_Ph);
    cudaGetSymbolAddress((void**)&pS,  g_S);

    cudaFuncSetAttribute(gemm_h16<0, false>, cudaFuncAttributeMaxDynamicSharedMemorySize, HSMEM);
    cudaFuncSetAttribute(gemm_h16<1, true >, cudaFuncAttributeMaxDynamicSharedMemorySize, HSMEM);
    cudaFuncSetAttribute(gemm_h16<2, true >, cudaFuncAttributeMaxDynamicSharedMemorySize, HSMEM);

    const float scale = 1.0f / sqrtf((float)DIM);

    // 0) convert x and weights to fp16
    cvt_f2h<<<(MSEQ * DIM) / (256 * 8), 256>>>(x, pxh, MSEQ * DIM);
    cvt_f2h<<<(DIM * DIM) / (256 * 8), 256>>>(Wq, pWq, DIM * DIM);
    cvt_f2h<<<(DIM * DIM) / (256 * 8), 256>>>(Wk, pWk, DIM * DIM);
    cvt_f2h<<<(DIM * DIM) / (256 * 8), 256>>>(Wv, pWv, DIM * DIM);

    // 1) QKV projections (fp16 in/out); scale folded into Q; V written transposed
    {
        dim3 g(DIM / BN, MSEQ / BM, 1);   // (4, 128, 1)
        gemm_h16<1, true><<<g, NTHREADS, HSMEM>>>(pxh, pWq, bq, pQ,  DIM, DIM, DIM, DIM, scale, 0, 0, 0);
        gemm_h16<1, true><<<g, NTHREADS, HSMEM>>>(pxh, pWk, bk, pK,  DIM, DIM, DIM, DIM, 1.0f,  0, 0, 0);
        gemm_h16<2, true><<<g, NTHREADS, HSMEM>>>(pxh, pWv, bv, pVT, DIM, DIM, 0,   DIM, 1.0f,  0, 0, 0);
    }

    // 2) scores[b] = Qs[b] @ K[b]^T  -> f32 S
    {
        dim3 g(SEQ / BN, SEQ / BM, BATCH);   // (16, 16, 8)
        gemm_h16<0, false><<<g, NTHREADS, HSMEM>>>(pQ, pK, nullptr, pS,
                                                   DIM, DIM, SEQ, DIM, 1.0f,
                                                   (long long)SEQ * DIM,
                                                   (long long)SEQ * DIM,
                                                   (long long)SEQ * SEQ);
    }

    // 3) masked softmax: S f32 -> P fp16
    softmax_h<<<BATCH * SEQ, 256>>>(pS, pP, mask);

    // 4) out[b] = P[b] @ VT[b]^T  (NT: VT is [DIM][SEQ] K-major), f32 out
    {
        dim3 g(DIM / BN, SEQ / BM, BATCH);   // (4, 16, 8)
        gemm_h16<0, false><<<g, NTHREADS, HSMEM>>>(pP, pVT, nullptr, out,
                                                   SEQ, SEQ, DIM, SEQ, 1.0f,
                                                   (long long)SEQ * SEQ,
                                                   (long long)DIM * SEQ,
                                                   (long long)SEQ * DIM);
    }
}